// round 11
// baseline (speedup 1.0000x reference)
#include <cuda_runtime.h>
#include <cstdint>

// Problem shape (fixed): x [T,B,C,H,W], T=4,B=16,C=512,H=W=32 -> N=1024
#define TT 4
#define BB 16
#define CC 512
#define NN 1024
#define HEADS 8
#define DD 64
#define VTH 1.0f

#define BCN  ((size_t)BB * CC * NN)          // 8,388,608
#define TBCN ((size_t)TT * BB * CC * NN)     // 33,554,432
#define NROW ((size_t)TT * BB * CC)          // 32768 spike rows per matrix

// ---------------- scratch (static device globals; no runtime allocation) ----
__device__ float g_S[TBCN];          // Q spikes only
__device__ float g_Sa[TBCN];         // attention spikes
__device__ float g_kv[(size_t)TT * BB * HEADS * DD * DD];
__device__ float g_Wt[4ull * CC * CC];   // pre-transposed weights [mat][c][o]
__device__ uint32_t g_Kb[NROW * 32];     // K spikes bitpacked over n
__device__ uint32_t g_Vb[NROW * 32];     // V spikes bitpacked over n

// ===================== helpers =============================================
__device__ __forceinline__ uint32_t smem_u32(const void* p) {
    uint32_t a;
    asm("{ .reg .u64 t; cvta.to.shared.u64 t, %1; cvt.u32.u64 %0, t; }"
        : "=r"(a) : "l"(p));
    return a;
}
__device__ __forceinline__ void cp_async16(uint32_t dst, const void* src) {
    asm volatile("cp.async.cg.shared.global [%0], [%1], 16;"
                 :: "r"(dst), "l"(src));
}
#define CP_COMMIT() asm volatile("cp.async.commit_group;" ::: "memory")
#define CP_WAIT1()  asm volatile("cp.async.wait_group 1;" ::: "memory")
#define CP_WAIT0()  asm volatile("cp.async.wait_group 0;" ::: "memory")

// ---------------------------------------------------------------------------
// W transpose: Wt[mat][c][o] = W[mat][o][c]   (one-shot, 4 MB)
// ---------------------------------------------------------------------------
__global__ void wtrans_kernel(const float* __restrict__ W0, const float* __restrict__ W1,
                              const float* __restrict__ W2, const float* __restrict__ W3)
{
    __shared__ float tile[32][33];
    const int mat = blockIdx.z;
    const float* W = (mat == 0) ? W0 : (mat == 1) ? W1 : (mat == 2) ? W2 : W3;
    const int o0 = blockIdx.x * 32, c0 = blockIdx.y * 32;
    const int t = threadIdx.x;
    const int r = t >> 3, cg = (t & 7) * 4;
    {
        float4 v = *(const float4*)(W + (size_t)(o0 + r) * CC + c0 + cg);
        tile[r][cg + 0] = v.x; tile[r][cg + 1] = v.y;
        tile[r][cg + 2] = v.z; tile[r][cg + 3] = v.w;
    }
    __syncthreads();
    {
        float4 v;
        v.x = tile[cg + 0][r]; v.y = tile[cg + 1][r];
        v.z = tile[cg + 2][r]; v.w = tile[cg + 3][r];
        *(float4*)(g_Wt + (size_t)mat * CC * CC + (size_t)(c0 + r) * CC + o0 + cg) = v;
    }
}

// ---------------------------------------------------------------------------
// Uniform fused conv1x1 GEMM + LIF (round-8 inner loop; ptxas scheduling).
// CONN=0, mat=0 (Q): spikes -> g_S as floats.
// CONN=0, mat=1,2 (K,V): spikes bit-packed in-kernel -> g_Kb/g_Vb. No float
//   write, no separate pack pass. Packing uses the dead Xs/Ws smem as a
//   byte staging tile (stride 132 rows, bank-conflict-free), then warp
//   ballots; bit convention identical to the old pack_kernel.
// CONN=1 (proj): charge = Y + x shortcut -> final spikes to Out.
// Tile 128(o) x 128(n), BK=16, 256 thr, 8x8 microtile split {lo,hi+64}.
// Per-output accumulation sequential over c — bit-exact vs reference chain.
// Dynamic smem: Xs 2x[16][128] + Ws 2x[16][128] + Vs[64][256] = 96 KB.
// ---------------------------------------------------------------------------
template <int CONN>
__global__ __launch_bounds__(256, 2)
void gemm_lif(const float* __restrict__ In,
              const float* __restrict__ WtAll, int matofs,
              const float* __restrict__ b0, const float* __restrict__ b1,
              const float* __restrict__ b2,
              const float* __restrict__ xsc,
              float* __restrict__ Out)
{
    extern __shared__ float sm[];
    float* Xs = sm;            // 2 stages x [16][128]
    float* Ws = sm + 4096;     // 2 stages x [16][128]
    float* Vs = sm + 8192;     // [64][256]
    unsigned char* spb = (unsigned char*)sm;   // byte tile 128 x (stride 132)
    const uint32_t xs_b = smem_u32(Xs), ws_b = smem_u32(Ws);

    const int tid = threadIdx.x, tx = tid & 15, ty = tid >> 4;
    const int z = blockIdx.z;
    const int mat = CONN ? 0 : (z >> 4);
    const int b = CONN ? z : (z & 15);
    const int n0 = blockIdx.x * 128, o0 = blockIdx.y * 128;

    const float* Wt = WtAll + (size_t)(matofs + mat) * CC * CC;
    const float* bias = (mat == 0) ? b0 : (mat == 1) ? b1 : b2;

    float bb[8];
#pragma unroll
    for (int i = 0; i < 4; i++) {
        bb[i] = bias[o0 + ty * 4 + i];
        bb[4 + i] = bias[o0 + 64 + ty * 4 + i];
    }

    const int lr = tid >> 4;           // fill row 0..15
    const int lc = (tid & 15) * 8;     // fill col base (8 floats = 2x16B)

    for (int t = 0; t < TT; t++) {
        const float* Xb = In + (size_t)(t * BB + b) * CC * NN;

        float acc[8][8];
#pragma unroll
        for (int i = 0; i < 8; i++)
#pragma unroll
            for (int j = 0; j < 8; j++) acc[i][j] = 0.f;

        // prologue fill k-tile 0
        {
            const float* xp = Xb + (size_t)lr * NN + n0 + lc;
            uint32_t xd = xs_b + (uint32_t)(lr * 128 + lc) * 4;
            cp_async16(xd, xp); cp_async16(xd + 16, xp + 4);
            const float* wp = Wt + (size_t)lr * CC + o0 + lc;
            uint32_t wd = ws_b + (uint32_t)(lr * 128 + lc) * 4;
            cp_async16(wd, wp); cp_async16(wd + 16, wp + 4);
            CP_COMMIT();
        }

        for (int kt = 0; kt < 32; kt++) {
            if (kt < 31) {
                const int s = (kt + 1) & 1;
                const int k0 = (kt + 1) * 16;
                const float* xp = Xb + (size_t)(k0 + lr) * NN + n0 + lc;
                uint32_t xd = xs_b + (uint32_t)(s * 2048 + lr * 128 + lc) * 4;
                cp_async16(xd, xp); cp_async16(xd + 16, xp + 4);
                const float* wp = Wt + (size_t)(k0 + lr) * CC + o0 + lc;
                uint32_t wd = ws_b + (uint32_t)(s * 2048 + lr * 128 + lc) * 4;
                cp_async16(wd, wp); cp_async16(wd + 16, wp + 4);
                CP_COMMIT();
                CP_WAIT1();
            } else {
                CP_WAIT0();
            }
            __syncthreads();

            const float* Xst = Xs + (kt & 1) * 2048;
            const float* Wst = Ws + (kt & 1) * 2048;
#pragma unroll
            for (int kk = 0; kk < 16; kk++) {
                float4 xa = *(const float4*)(Xst + kk * 128 + tx * 4);
                float4 xc = *(const float4*)(Xst + kk * 128 + 64 + tx * 4);
                float4 wa = *(const float4*)(Wst + kk * 128 + ty * 4);
                float4 wc = *(const float4*)(Wst + kk * 128 + 64 + ty * 4);
                float xv[8] = {xa.x, xa.y, xa.z, xa.w, xc.x, xc.y, xc.z, xc.w};
                float wv[8] = {wa.x, wa.y, wa.z, wa.w, wc.x, wc.y, wc.z, wc.w};
#pragma unroll
                for (int i = 0; i < 8; i++)
#pragma unroll
                    for (int j = 0; j < 8; j++)
                        acc[i][j] += wv[i] * xv[j];
            }
            __syncthreads();
        }

        // ---- epilogue: bias (+shortcut) + LIF; v persists in smem ----
        const size_t tbofs = (size_t)(t * BB + b) * CC * NN;
        if (CONN || mat == 0) {
            // float spike output path (Q spikes / final output)
#pragma unroll
            for (int i = 0; i < 8; i++) {
                const int o = o0 + ((i < 4) ? (ty * 4 + i) : (64 + ty * 4 + i - 4));
                const size_t rowb = tbofs + (size_t)o * NN + n0;
#pragma unroll
                for (int hf = 0; hf < 2; hf++) {
                    const int nc = hf ? (64 + tx * 4) : (tx * 4);
                    float4 xs4;
                    if (CONN) xs4 = *(const float4*)(xsc + rowb + nc);
                    float4 r;
#pragma unroll
                    for (int j = 0; j < 4; j++) {
                        const int vi = i * 8 + hf * 4 + j;
                        float v = (t == 0) ? 0.f : Vs[vi * 256 + tid];
                        float p = acc[i][hf * 4 + j] + bb[i];
                        float chg = CONN ? (p + ((const float*)&xs4)[j]) : p;
                        v = v + (chg - v) * 0.5f;
                        float s = (v >= VTH) ? 1.f : 0.f;
                        Vs[vi * 256 + tid] = (s != 0.f) ? 0.f : v;
                        ((float*)&r)[j] = s;
                    }
                    *(float4*)(Out + rowb + nc) = r;
                }
            }
        } else {
            // K/V path: spikes -> smem bytes -> warp-ballot bitpack
#pragma unroll
            for (int i = 0; i < 8; i++) {
                const int ol = (i < 4) ? (ty * 4 + i) : (64 + ty * 4 + i - 4);
#pragma unroll
                for (int hf = 0; hf < 2; hf++) {
                    const int nc = hf ? (64 + tx * 4) : (tx * 4);
                    uchar4 bs;
#pragma unroll
                    for (int j = 0; j < 4; j++) {
                        const int vi = i * 8 + hf * 4 + j;
                        float v = (t == 0) ? 0.f : Vs[vi * 256 + tid];
                        float p = acc[i][hf * 4 + j] + bb[i];
                        v = v + (p - v) * 0.5f;
                        float s = (v >= VTH) ? 1.f : 0.f;
                        Vs[vi * 256 + tid] = (s != 0.f) ? 0.f : v;
                        ((unsigned char*)&bs)[j] = (s != 0.f) ? 1 : 0;
                    }
                    *(uchar4*)(spb + ol * 132 + nc) = bs;
                }
            }
            __syncthreads();
            {
                const int wp = tid >> 5, lane = tid & 31;
                uint32_t* dstb = (mat == 1 ? g_Kb : g_Vb)
                    + ((size_t)(t * BB + b) * CC + o0) * 32 + (n0 >> 5);
#pragma unroll
                for (int rr = 0; rr < 16; rr++) {
                    const int row = wp * 16 + rr;
#pragma unroll
                    for (int w = 0; w < 4; w++) {
                        uint32_t m = __ballot_sync(0xFFFFFFFFu,
                            spb[row * 132 + w * 32 + lane] != 0);
                        if (lane == 0) dstb[(size_t)row * 32 + w] = m;
                    }
                }
            }
            __syncthreads();   // spb dead before next t's cp_async fills Xs
        }
    }
}

// ---------------------------------------------------------------------------
// kv[tbh][d][e] = popc over n of (K[d] & V[e])  — bit-exact integer counts.
// ---------------------------------------------------------------------------
__global__ __launch_bounds__(256)
void kv_pop_kernel()
{
    __shared__ uint32_t Ks[64 * 33];
    __shared__ uint32_t Vt[32 * 68];

    const int tbh = blockIdx.x;
    const int tb = tbh >> 3;
    const int h = tbh & 7;
    const size_t rowb = ((size_t)tb * CC + h * DD) * 32;   // word offset
    const int tid = threadIdx.x;

#pragma unroll
    for (int q = 0; q < 2; q++) {
        const int wi = (q * 256 + tid) * 4;
        uint4 kv4 = *(const uint4*)(g_Kb + rowb + wi);
        uint4 vv4 = *(const uint4*)(g_Vb + rowb + wi);
        const uint32_t ka[4] = {kv4.x, kv4.y, kv4.z, kv4.w};
        const uint32_t va[4] = {vv4.x, vv4.y, vv4.z, vv4.w};
#pragma unroll
        for (int i = 0; i < 4; i++) {
            const int W = wi + i, d = W >> 5, w = W & 31;
            Ks[d * 33 + w] = ka[i];
            Vt[w * 68 + d] = va[i];
        }
    }
    __syncthreads();

    const int d = tid >> 2;
    const int eb = (tid & 3) * 16;
    int cnt[16];
#pragma unroll
    for (int i = 0; i < 16; i++) cnt[i] = 0;

#pragma unroll 4
    for (int w = 0; w < 32; w++) {
        const uint32_t kd = Ks[d * 33 + w];
        const uint32_t* vr = &Vt[w * 68 + eb];
#pragma unroll
        for (int g = 0; g < 4; g++) {
            uint4 v4 = *(const uint4*)(vr + g * 4);
            cnt[g * 4 + 0] += __popc(kd & v4.x);
            cnt[g * 4 + 1] += __popc(kd & v4.y);
            cnt[g * 4 + 2] += __popc(kd & v4.z);
            cnt[g * 4 + 3] += __popc(kd & v4.w);
        }
    }

    float* kvout = g_kv + (size_t)tbh * DD * DD + (size_t)d * DD + eb;
#pragma unroll
    for (int g = 0; g < 4; g++) {
        float4 r = {(float)cnt[g * 4 + 0], (float)cnt[g * 4 + 1],
                    (float)cnt[g * 4 + 2], (float)cnt[g * 4 + 3]};
        *(float4*)(kvout + g * 4) = r;
    }
}

// ---------------------------------------------------------------------------
// Fused attention output + LIF. Block (n-tile 64, bh), loop t.
// ---------------------------------------------------------------------------
__global__ __launch_bounds__(256)
void attn_lif_kernel()
{
    const int bh = blockIdx.y;
    const int b = bh >> 3;
    const int h = bh & 7;
    const int n0 = blockIdx.x * 64;

    __shared__ __align__(16) float kvs[DD][DD + 4];
    __shared__ __align__(16) float Qs[16][64];

    const int tid = threadIdx.x;
    const int tx = tid & 15, ty = tid >> 4;

    float v[4][4];
#pragma unroll
    for (int i = 0; i < 4; i++)
#pragma unroll
        for (int j = 0; j < 4; j++) v[i][j] = 0.f;

    for (int t = 0; t < TT; t++) {
        const int tb = t * BB + b;
        const float* Q_ = g_S + ((size_t)tb * CC + h * DD) * NN;
        const float* kvp = g_kv + (size_t)(t * 128 + bh) * DD * DD;

#pragma unroll
        for (int r = 0; r < 4; r++) {
            int fid = r * 256 + tid;
            int dd = fid >> 4;
            int eg = (fid & 15) * 4;
            float4 vv = *(const float4*)(kvp + (size_t)dd * DD + eg);
            *(float4*)(&kvs[dd][eg]) = vv;
        }
        __syncthreads();

        float acc[4][4] = {};
        for (int d0 = 0; d0 < DD; d0 += 16) {
            int qr = tid >> 4;
            int qc = (tid & 15) * 4;
            float4 qv = *(const float4*)(Q_ + (size_t)(d0 + qr) * NN + n0 + qc);
            *(float4*)(&Qs[qr][qc]) = qv;
            __syncthreads();
#pragma unroll
            for (int kk = 0; kk < 16; kk++) {
                float4 qf = *(const float4*)(&Qs[kk][tx * 4]);
                float4 kf = *(const float4*)(&kvs[d0 + kk][ty * 4]);
                float qa[4] = {qf.x, qf.y, qf.z, qf.w};
                float ka[4] = {kf.x, kf.y, kf.z, kf.w};
#pragma unroll
                for (int i = 0; i < 4; i++)
#pragma unroll
                    for (int j = 0; j < 4; j++)
                        acc[i][j] += ka[i] * qa[j];
            }
            __syncthreads();
        }

#pragma unroll
        for (int i = 0; i < 4; i++) {
            const int e = ty * 4 + i;
            float4 r;
#pragma unroll
            for (int j = 0; j < 4; j++) {
                float xx = acc[i][j] * 0.125f;
                float vv = v[i][j];
                vv = vv + (xx - vv) * 0.5f;
                float s = (vv >= VTH) ? 1.f : 0.f;
                v[i][j] = (s != 0.f) ? 0.f : vv;
                ((float*)&r)[j] = s;
            }
            *(float4*)(g_Sa + ((size_t)tb * CC + h * DD + e) * NN + n0 + tx * 4) = r;
        }
    }
}

// ---------------------------------------------------------------------------
extern "C" void kernel_launch(void* const* d_in, const int* in_sizes, int n_in,
                              void* d_out, int out_size)
{
    const float* x  = (const float*)d_in[0];
    const float* Wq = (const float*)d_in[1];
    const float* bq = (const float*)d_in[2];
    const float* Wk = (const float*)d_in[3];
    const float* bk = (const float*)d_in[4];
    const float* Wv = (const float*)d_in[5];
    const float* bv = (const float*)d_in[6];
    const float* Wp = (const float*)d_in[7];
    const float* bp = (const float*)d_in[8];
    float* out = (float*)d_out;

    void *pS, *pSa, *pWt;
    cudaGetSymbolAddress(&pS, g_S);
    cudaGetSymbolAddress(&pSa, g_Sa);
    cudaGetSymbolAddress(&pWt, g_Wt);

    const int GL_SMEM = (8192 + 16384) * 4;  // 98304 bytes
    cudaFuncSetAttribute(gemm_lif<0>, cudaFuncAttributeMaxDynamicSharedMemorySize, GL_SMEM);
    cudaFuncSetAttribute(gemm_lif<1>, cudaFuncAttributeMaxDynamicSharedMemorySize, GL_SMEM);

    // 1. one-shot weight transpose (Wt[c][o])
    wtrans_kernel<<<dim3(16, 16, 4), 256>>>(Wq, Wk, Wv, Wp);
    // 2. fused QKV conv GEMM + LIF; K/V spikes bit-packed in-kernel
    gemm_lif<0><<<dim3(8, 4, 48), 256, GL_SMEM>>>(
        x, (const float*)pWt, 0, bq, bk, bv, nullptr, (float*)pS);
    // 3. kv via AND+popcount (bit-exact integer counts)
    kv_pop_kernel<<<TT * BB * HEADS, 256>>>();
    // 4. fused attention output + LIF
    attn_lif_kernel<<<dim3(NN / 64, BB * HEADS), 256>>>();
    // 5. fused proj conv GEMM + connecting LIF -> final spikes
    gemm_lif<1><<<dim3(8, 4, 16), 256, GL_SMEM>>>(
        (const float*)pSa, (const float*)pWt, 3, bp, bp, bp, x, out);
}

// round 12
// speedup vs baseline: 1.0186x; 1.0186x over previous
#include <cuda_runtime.h>
#include <cstdint>

// Problem shape (fixed): x [T,B,C,H,W], T=4,B=16,C=512,H=W=32 -> N=1024
#define TT 4
#define BB 16
#define CC 512
#define NN 1024
#define HEADS 8
#define DD 64
#define VTH 1.0f

#define BCN  ((size_t)BB * CC * NN)          // 8,388,608
#define TBCN ((size_t)TT * BB * CC * NN)     // 33,554,432
#define NROW ((size_t)TT * BB * CC)          // 32768 spike rows per matrix

// ---------------- scratch (static device globals; no runtime allocation) ----
__device__ float g_S[3ull * TBCN];   // spikes q,k,v
__device__ float g_Sa[TBCN];         // attention spikes
__device__ float g_kv[(size_t)TT * BB * HEADS * DD * DD];
__device__ float g_Wt[4ull * CC * CC];   // pre-transposed weights [mat][c][o]
__device__ uint32_t g_Kb[NROW * 32];     // K spikes bitpacked over n
__device__ uint32_t g_Vb[NROW * 32];     // V spikes bitpacked over n

// ===================== helpers =============================================
__device__ __forceinline__ uint32_t smem_u32(const void* p) {
    uint32_t a;
    asm("{ .reg .u64 t; cvta.to.shared.u64 t, %1; cvt.u32.u64 %0, t; }"
        : "=r"(a) : "l"(p));
    return a;
}
__device__ __forceinline__ void cp_async16(uint32_t dst, const void* src) {
    asm volatile("cp.async.cg.shared.global [%0], [%1], 16;"
                 :: "r"(dst), "l"(src));
}
#define CP_COMMIT() asm volatile("cp.async.commit_group;" ::: "memory")
#define CP_WAIT1()  asm volatile("cp.async.wait_group 1;" ::: "memory")
#define CP_WAIT0()  asm volatile("cp.async.wait_group 0;" ::: "memory")

// ---------------------------------------------------------------------------
// W transpose: Wt[mat][c][o] = W[mat][o][c]   (one-shot, 4 MB)
// ---------------------------------------------------------------------------
__global__ void wtrans_kernel(const float* __restrict__ W0, const float* __restrict__ W1,
                              const float* __restrict__ W2, const float* __restrict__ W3)
{
    __shared__ float tile[32][33];
    const int mat = blockIdx.z;
    const float* W = (mat == 0) ? W0 : (mat == 1) ? W1 : (mat == 2) ? W2 : W3;
    const int o0 = blockIdx.x * 32, c0 = blockIdx.y * 32;
    const int t = threadIdx.x;
    const int r = t >> 3, cg = (t & 7) * 4;
    {
        float4 v = *(const float4*)(W + (size_t)(o0 + r) * CC + c0 + cg);
        tile[r][cg + 0] = v.x; tile[r][cg + 1] = v.y;
        tile[r][cg + 2] = v.z; tile[r][cg + 3] = v.w;
    }
    __syncthreads();
    {
        float4 v;
        v.x = tile[cg + 0][r]; v.y = tile[cg + 1][r];
        v.z = tile[cg + 2][r]; v.w = tile[cg + 3][r];
        *(float4*)(g_Wt + (size_t)mat * CC * CC + (size_t)(c0 + r) * CC + o0 + cg) = v;
    }
}

// ---------------------------------------------------------------------------
// Uniform fused conv1x1 GEMM + LIF — 3-stage rolling cp.async pipeline.
// Y[o,n] = sum_c W[o,c]*In[c,n] + bias[o] ; LIF over t (v in smem, private
// per thread -> no barrier around epilogue).
// Rolling iteration g = t*32 + kt over all TT*32 = 128 k-tiles: the pipeline
// never drains at t boundaries; ONE __syncthreads per iteration (placed
// before the stage-(g+2) prefetch, which protects the buffer read at g-1).
// CONN=1: charge = Y + x (shortcut) -> final spikes to Out.
// CONN=0: spikes -> Out + mat*TBCN (q,k,v).
// Tile 128(o) x 128(n), BK=16, 256 thr, 8x8 microtile split {lo,hi+64}.
// Per-output accumulation sequential over c — bit-exact vs reference chain.
// Dynamic smem: Xs 3x[16][128] + Ws 3x[16][128] + Vs[64][256] = 112 KB.
// ---------------------------------------------------------------------------
template <int CONN>
__global__ __launch_bounds__(256, 2)
void gemm_lif(const float* __restrict__ In,
              const float* __restrict__ WtAll, int matofs,
              const float* __restrict__ b0, const float* __restrict__ b1,
              const float* __restrict__ b2,
              const float* __restrict__ xsc,
              float* __restrict__ Out)
{
    extern __shared__ float sm[];
    float* Xs = sm;            // 3 stages x [16][128]
    float* Ws = sm + 6144;     // 3 stages x [16][128]
    float* Vs = sm + 12288;    // [64][256]
    const uint32_t xs_b = smem_u32(Xs), ws_b = smem_u32(Ws);

    const int tid = threadIdx.x, tx = tid & 15, ty = tid >> 4;
    const int z = blockIdx.z;
    const int mat = CONN ? 0 : (z >> 4);
    const int b = CONN ? z : (z & 15);
    const int n0 = blockIdx.x * 128, o0 = blockIdx.y * 128;

    const float* Wt = WtAll + (size_t)(matofs + mat) * CC * CC;
    const float* bias = (mat == 0) ? b0 : (mat == 1) ? b1 : b2;
    float* outb = Out + (CONN ? 0 : (size_t)mat * TBCN);

    float bb[8];
#pragma unroll
    for (int i = 0; i < 4; i++) {
        bb[i] = bias[o0 + ty * 4 + i];
        bb[4 + i] = bias[o0 + 64 + ty * 4 + i];
    }

    const int lr = tid >> 4;           // fill row 0..15
    const int lc = (tid & 15) * 8;     // fill col base (8 floats = 2x16B)

    // prefetch of global iteration gg into stage buffer s
    auto prefetch = [&](int gg, int s) {
        const int tt = gg >> 5;
        const int k0 = (gg & 31) << 4;
        const float* Xb = In + (size_t)(tt * BB + b) * CC * NN;
        const float* xp = Xb + (size_t)(k0 + lr) * NN + n0 + lc;
        uint32_t xd = xs_b + (uint32_t)(s * 2048 + lr * 128 + lc) * 4;
        cp_async16(xd, xp); cp_async16(xd + 16, xp + 4);
        const float* wp = Wt + (size_t)(k0 + lr) * CC + o0 + lc;
        uint32_t wd = ws_b + (uint32_t)(s * 2048 + lr * 128 + lc) * 4;
        cp_async16(wd, wp); cp_async16(wd + 16, wp + 4);
        CP_COMMIT();
    };

    float acc[8][8];
#pragma unroll
    for (int i = 0; i < 8; i++)
#pragma unroll
        for (int j = 0; j < 8; j++) acc[i][j] = 0.f;

    // prologue: fill stages for g=0, g=1
    prefetch(0, 0);
    prefetch(1, 1);

    int cur = 0, pf = 2;   // cur = g%3, pf = (g+2)%3
    const int NG = TT * 32;  // 128

    for (int g = 0; g < NG; g++) {
        if (g < NG - 1) CP_WAIT1(); else CP_WAIT0();
        __syncthreads();                 // protects buffer pf (read at g-1)
        if (g + 2 < NG) prefetch(g + 2, pf);

        const float* Xst = Xs + cur * 2048;
        const float* Wst = Ws + cur * 2048;
#pragma unroll
        for (int kk = 0; kk < 16; kk++) {
            float4 xa = *(const float4*)(Xst + kk * 128 + tx * 4);
            float4 xc = *(const float4*)(Xst + kk * 128 + 64 + tx * 4);
            float4 wa = *(const float4*)(Wst + kk * 128 + ty * 4);
            float4 wc = *(const float4*)(Wst + kk * 128 + 64 + ty * 4);
            float xv[8] = {xa.x, xa.y, xa.z, xa.w, xc.x, xc.y, xc.z, xc.w};
            float wv[8] = {wa.x, wa.y, wa.z, wa.w, wc.x, wc.y, wc.z, wc.w};
#pragma unroll
            for (int i = 0; i < 8; i++)
#pragma unroll
                for (int j = 0; j < 8; j++)
                    acc[i][j] += wv[i] * xv[j];
        }

        if ((g & 31) == 31) {
            // ---- epilogue for t = g>>5: bias (+shortcut) + LIF + spikes ----
            const int t = g >> 5;
            const size_t tbofs = (size_t)(t * BB + b) * CC * NN;
#pragma unroll
            for (int i = 0; i < 8; i++) {
                const int o = o0 + ((i < 4) ? (ty * 4 + i) : (64 + ty * 4 + i - 4));
                const size_t rowb = tbofs + (size_t)o * NN + n0;
#pragma unroll
                for (int hf = 0; hf < 2; hf++) {
                    const int nc = hf ? (64 + tx * 4) : (tx * 4);
                    float4 xs4;
                    if (CONN) xs4 = *(const float4*)(xsc + rowb + nc);
                    float4 r;
#pragma unroll
                    for (int j = 0; j < 4; j++) {
                        const int vi = i * 8 + hf * 4 + j;
                        float v = (t == 0) ? 0.f : Vs[vi * 256 + tid];
                        float p = acc[i][hf * 4 + j] + bb[i];
                        float chg = CONN ? (p + ((const float*)&xs4)[j]) : p;
                        v = v + (chg - v) * 0.5f;
                        float s = (v >= VTH) ? 1.f : 0.f;
                        Vs[vi * 256 + tid] = (s != 0.f) ? 0.f : v;
                        ((float*)&r)[j] = s;
                    }
                    *(float4*)(outb + rowb + nc) = r;
                }
            }
#pragma unroll
            for (int i = 0; i < 8; i++)
#pragma unroll
                for (int j = 0; j < 8; j++) acc[i][j] = 0.f;
        }

        // rotate stage indices
        cur = (cur == 2) ? 0 : cur + 1;
        pf = (pf == 2) ? 0 : pf + 1;
    }
}

// ---------------------------------------------------------------------------
// Bitpack k/v spikes over n: g_Kb/g_Vb[row][w], bit l of word w = spike at
// n = w*32+l. One warp per row; ballot over coalesced 128B loads.
// ---------------------------------------------------------------------------
__global__ void pack_kernel()
{
    const int warp = threadIdx.x >> 5, lane = threadIdx.x & 31;
    const size_t row = (size_t)blockIdx.x * 8 + warp;     // 0..NROW-1
    const int which = blockIdx.y;                          // 0 = K, 1 = V
    const float* src = g_S + (size_t)(which + 1) * TBCN + row * NN;
    uint32_t* dst = (which ? g_Vb : g_Kb) + row * 32;
#pragma unroll
    for (int w = 0; w < 32; w++) {
        float f = src[w * 32 + lane];
        uint32_t m = __ballot_sync(0xFFFFFFFFu, f != 0.f);
        if (lane == 0) dst[w] = m;
    }
}

// ---------------------------------------------------------------------------
// kv[tbh][d][e] = popc over n of (K[d] & V[e])  — bit-exact integer counts.
// ---------------------------------------------------------------------------
__global__ __launch_bounds__(256)
void kv_pop_kernel()
{
    __shared__ uint32_t Ks[64 * 33];
    __shared__ uint32_t Vt[32 * 68];

    const int tbh = blockIdx.x;
    const int tb = tbh >> 3;
    const int h = tbh & 7;
    const size_t rowb = ((size_t)tb * CC + h * DD) * 32;   // word offset
    const int tid = threadIdx.x;

#pragma unroll
    for (int q = 0; q < 2; q++) {
        const int wi = (q * 256 + tid) * 4;
        uint4 kv4 = *(const uint4*)(g_Kb + rowb + wi);
        uint4 vv4 = *(const uint4*)(g_Vb + rowb + wi);
        const uint32_t ka[4] = {kv4.x, kv4.y, kv4.z, kv4.w};
        const uint32_t va[4] = {vv4.x, vv4.y, vv4.z, vv4.w};
#pragma unroll
        for (int i = 0; i < 4; i++) {
            const int W = wi + i, d = W >> 5, w = W & 31;
            Ks[d * 33 + w] = ka[i];
            Vt[w * 68 + d] = va[i];
        }
    }
    __syncthreads();

    const int d = tid >> 2;
    const int eb = (tid & 3) * 16;
    int cnt[16];
#pragma unroll
    for (int i = 0; i < 16; i++) cnt[i] = 0;

#pragma unroll 4
    for (int w = 0; w < 32; w++) {
        const uint32_t kd = Ks[d * 33 + w];
        const uint32_t* vr = &Vt[w * 68 + eb];
#pragma unroll
        for (int g = 0; g < 4; g++) {
            uint4 v4 = *(const uint4*)(vr + g * 4);
            cnt[g * 4 + 0] += __popc(kd & v4.x);
            cnt[g * 4 + 1] += __popc(kd & v4.y);
            cnt[g * 4 + 2] += __popc(kd & v4.z);
            cnt[g * 4 + 3] += __popc(kd & v4.w);
        }
    }

    float* kvout = g_kv + (size_t)tbh * DD * DD + (size_t)d * DD + eb;
#pragma unroll
    for (int g = 0; g < 4; g++) {
        float4 r = {(float)cnt[g * 4 + 0], (float)cnt[g * 4 + 1],
                    (float)cnt[g * 4 + 2], (float)cnt[g * 4 + 3]};
        *(float4*)(kvout + g * 4) = r;
    }
}

// ---------------------------------------------------------------------------
// Fused attention output + LIF. Block (n-tile 64, bh), loop t.
// ---------------------------------------------------------------------------
__global__ __launch_bounds__(256)
void attn_lif_kernel()
{
    const int bh = blockIdx.y;
    const int b = bh >> 3;
    const int h = bh & 7;
    const int n0 = blockIdx.x * 64;

    __shared__ __align__(16) float kvs[DD][DD + 4];
    __shared__ __align__(16) float Qs[16][64];

    const int tid = threadIdx.x;
    const int tx = tid & 15, ty = tid >> 4;

    float v[4][4];
#pragma unroll
    for (int i = 0; i < 4; i++)
#pragma unroll
        for (int j = 0; j < 4; j++) v[i][j] = 0.f;

    for (int t = 0; t < TT; t++) {
        const int tb = t * BB + b;
        const float* Q_ = g_S + ((size_t)tb * CC + h * DD) * NN;
        const float* kvp = g_kv + (size_t)(t * 128 + bh) * DD * DD;

#pragma unroll
        for (int r = 0; r < 4; r++) {
            int fid = r * 256 + tid;
            int dd = fid >> 4;
            int eg = (fid & 15) * 4;
            float4 vv = *(const float4*)(kvp + (size_t)dd * DD + eg);
            *(float4*)(&kvs[dd][eg]) = vv;
        }
        __syncthreads();

        float acc[4][4] = {};
        for (int d0 = 0; d0 < DD; d0 += 16) {
            int qr = tid >> 4;
            int qc = (tid & 15) * 4;
            float4 qv = *(const float4*)(Q_ + (size_t)(d0 + qr) * NN + n0 + qc);
            *(float4*)(&Qs[qr][qc]) = qv;
            __syncthreads();
#pragma unroll
            for (int kk = 0; kk < 16; kk++) {
                float4 qf = *(const float4*)(&Qs[kk][tx * 4]);
                float4 kf = *(const float4*)(&kvs[d0 + kk][ty * 4]);
                float qa[4] = {qf.x, qf.y, qf.z, qf.w};
                float ka[4] = {kf.x, kf.y, kf.z, kf.w};
#pragma unroll
                for (int i = 0; i < 4; i++)
#pragma unroll
                    for (int j = 0; j < 4; j++)
                        acc[i][j] += ka[i] * qa[j];
            }
            __syncthreads();
        }

#pragma unroll
        for (int i = 0; i < 4; i++) {
            const int e = ty * 4 + i;
            float4 r;
#pragma unroll
            for (int j = 0; j < 4; j++) {
                float xx = acc[i][j] * 0.125f;
                float vv = v[i][j];
                vv = vv + (xx - vv) * 0.5f;
                float s = (vv >= VTH) ? 1.f : 0.f;
                v[i][j] = (s != 0.f) ? 0.f : vv;
                ((float*)&r)[j] = s;
            }
            *(float4*)(g_Sa + ((size_t)tb * CC + h * DD + e) * NN + n0 + tx * 4) = r;
        }
    }
}

// ---------------------------------------------------------------------------
extern "C" void kernel_launch(void* const* d_in, const int* in_sizes, int n_in,
                              void* d_out, int out_size)
{
    const float* x  = (const float*)d_in[0];
    const float* Wq = (const float*)d_in[1];
    const float* bq = (const float*)d_in[2];
    const float* Wk = (const float*)d_in[3];
    const float* bk = (const float*)d_in[4];
    const float* Wv = (const float*)d_in[5];
    const float* bv = (const float*)d_in[6];
    const float* Wp = (const float*)d_in[7];
    const float* bp = (const float*)d_in[8];
    float* out = (float*)d_out;

    void *pS, *pSa, *pWt;
    cudaGetSymbolAddress(&pS, g_S);
    cudaGetSymbolAddress(&pSa, g_Sa);
    cudaGetSymbolAddress(&pWt, g_Wt);

    const int GL_SMEM = (12288 + 16384) * 4;  // 114688 bytes (3 stages + Vs)
    cudaFuncSetAttribute(gemm_lif<0>, cudaFuncAttributeMaxDynamicSharedMemorySize, GL_SMEM);
    cudaFuncSetAttribute(gemm_lif<1>, cudaFuncAttributeMaxDynamicSharedMemorySize, GL_SMEM);

    // 1. one-shot weight transpose (Wt[c][o])
    wtrans_kernel<<<dim3(16, 16, 4), 256>>>(Wq, Wk, Wv, Wp);
    // 2. fused QKV conv GEMM + LIF (q,k,v in one launch; bit-exact chains)
    gemm_lif<0><<<dim3(8, 4, 48), 256, GL_SMEM>>>(
        x, (const float*)pWt, 0, bq, bk, bv, nullptr, (float*)pS);
    // 3. bitpack k/v spikes over n
    pack_kernel<<<dim3((int)(NROW / 8), 2), 256>>>();
    // 4. kv via AND+popcount (bit-exact integer counts)
    kv_pop_kernel<<<TT * BB * HEADS, 256>>>();
    // 5. fused attention output + LIF
    attn_lif_kernel<<<dim3(NN / 64, BB * HEADS), 256>>>();
    // 6. fused proj conv GEMM + connecting LIF -> final spikes
    gemm_lif<1><<<dim3(8, 4, 16), 256, GL_SMEM>>>(
        (const float*)pSa, (const float*)pWt, 3, bp, bp, bp, x, out);
}

// round 13
// speedup vs baseline: 1.0600x; 1.0406x over previous
#include <cuda_runtime.h>
#include <cstdint>

// Problem shape (fixed): x [T,B,C,H,W], T=4,B=16,C=512,H=W=32 -> N=1024
#define TT 4
#define BB 16
#define CC 512
#define NN 1024
#define HEADS 8
#define DD 64
#define VTH 1.0f

#define BCN  ((size_t)BB * CC * NN)          // 8,388,608
#define TBCN ((size_t)TT * BB * CC * NN)     // 33,554,432

// ---------------- scratch (static device globals; no runtime allocation) ----
__device__ float g_S[3ull * TBCN];   // spikes q,k,v
__device__ float g_Sa[TBCN];         // attention spikes
__device__ float g_kv[(size_t)TT * BB * HEADS * DD * DD];
__device__ float g_Wt[4ull * CC * CC];   // pre-transposed weights [mat][c][o]

// ===================== helpers =============================================
__device__ __forceinline__ uint32_t smem_u32(const void* p) {
    uint32_t a;
    asm("{ .reg .u64 t; cvta.to.shared.u64 t, %1; cvt.u32.u64 %0, t; }"
        : "=r"(a) : "l"(p));
    return a;
}
__device__ __forceinline__ void cp_async16(uint32_t dst, const void* src) {
    asm volatile("cp.async.cg.shared.global [%0], [%1], 16;"
                 :: "r"(dst), "l"(src));
}
#define CP_COMMIT() asm volatile("cp.async.commit_group;" ::: "memory")
#define CP_WAIT1()  asm volatile("cp.async.wait_group 1;" ::: "memory")
#define CP_WAIT0()  asm volatile("cp.async.wait_group 0;" ::: "memory")

// ---------------------------------------------------------------------------
// W transpose: Wt[mat][c][o] = W[mat][o][c]   (one-shot, 4 MB)
// ---------------------------------------------------------------------------
__global__ void wtrans_kernel(const float* __restrict__ W0, const float* __restrict__ W1,
                              const float* __restrict__ W2, const float* __restrict__ W3)
{
    __shared__ float tile[32][33];
    const int mat = blockIdx.z;
    const float* W = (mat == 0) ? W0 : (mat == 1) ? W1 : (mat == 2) ? W2 : W3;
    const int o0 = blockIdx.x * 32, c0 = blockIdx.y * 32;
    const int t = threadIdx.x;
    const int r = t >> 3, cg = (t & 7) * 4;
    {
        float4 v = *(const float4*)(W + (size_t)(o0 + r) * CC + c0 + cg);
        tile[r][cg + 0] = v.x; tile[r][cg + 1] = v.y;
        tile[r][cg + 2] = v.z; tile[r][cg + 3] = v.w;
    }
    __syncthreads();
    {
        float4 v;
        v.x = tile[cg + 0][r]; v.y = tile[cg + 1][r];
        v.z = tile[cg + 2][r]; v.w = tile[cg + 3][r];
        *(float4*)(g_Wt + (size_t)mat * CC * CC + (size_t)(c0 + r) * CC + o0 + cg) = v;
    }
}

// ---------------------------------------------------------------------------
// Uniform fused conv1x1 GEMM + LIF — 3-stage rolling cp.async pipeline.
// (unchanged from round 12 — best measured config; bit-exact c-sequential)
// ---------------------------------------------------------------------------
template <int CONN>
__global__ __launch_bounds__(256, 2)
void gemm_lif(const float* __restrict__ In,
              const float* __restrict__ WtAll, int matofs,
              const float* __restrict__ b0, const float* __restrict__ b1,
              const float* __restrict__ b2,
              const float* __restrict__ xsc,
              float* __restrict__ Out)
{
    extern __shared__ float sm[];
    float* Xs = sm;            // 3 stages x [16][128]
    float* Ws = sm + 6144;     // 3 stages x [16][128]
    float* Vs = sm + 12288;    // [64][256]
    const uint32_t xs_b = smem_u32(Xs), ws_b = smem_u32(Ws);

    const int tid = threadIdx.x, tx = tid & 15, ty = tid >> 4;
    const int z = blockIdx.z;
    const int mat = CONN ? 0 : (z >> 4);
    const int b = CONN ? z : (z & 15);
    const int n0 = blockIdx.x * 128, o0 = blockIdx.y * 128;

    const float* Wt = WtAll + (size_t)(matofs + mat) * CC * CC;
    const float* bias = (mat == 0) ? b0 : (mat == 1) ? b1 : b2;
    float* outb = Out + (CONN ? 0 : (size_t)mat * TBCN);

    float bb[8];
#pragma unroll
    for (int i = 0; i < 4; i++) {
        bb[i] = bias[o0 + ty * 4 + i];
        bb[4 + i] = bias[o0 + 64 + ty * 4 + i];
    }

    const int lr = tid >> 4;           // fill row 0..15
    const int lc = (tid & 15) * 8;     // fill col base (8 floats = 2x16B)

    auto prefetch = [&](int gg, int s) {
        const int tt = gg >> 5;
        const int k0 = (gg & 31) << 4;
        const float* Xb = In + (size_t)(tt * BB + b) * CC * NN;
        const float* xp = Xb + (size_t)(k0 + lr) * NN + n0 + lc;
        uint32_t xd = xs_b + (uint32_t)(s * 2048 + lr * 128 + lc) * 4;
        cp_async16(xd, xp); cp_async16(xd + 16, xp + 4);
        const float* wp = Wt + (size_t)(k0 + lr) * CC + o0 + lc;
        uint32_t wd = ws_b + (uint32_t)(s * 2048 + lr * 128 + lc) * 4;
        cp_async16(wd, wp); cp_async16(wd + 16, wp + 4);
        CP_COMMIT();
    };

    float acc[8][8];
#pragma unroll
    for (int i = 0; i < 8; i++)
#pragma unroll
        for (int j = 0; j < 8; j++) acc[i][j] = 0.f;

    prefetch(0, 0);
    prefetch(1, 1);

    int cur = 0, pf = 2;
    const int NG = TT * 32;  // 128

    for (int g = 0; g < NG; g++) {
        if (g < NG - 1) CP_WAIT1(); else CP_WAIT0();
        __syncthreads();
        if (g + 2 < NG) prefetch(g + 2, pf);

        const float* Xst = Xs + cur * 2048;
        const float* Wst = Ws + cur * 2048;
#pragma unroll
        for (int kk = 0; kk < 16; kk++) {
            float4 xa = *(const float4*)(Xst + kk * 128 + tx * 4);
            float4 xc = *(const float4*)(Xst + kk * 128 + 64 + tx * 4);
            float4 wa = *(const float4*)(Wst + kk * 128 + ty * 4);
            float4 wc = *(const float4*)(Wst + kk * 128 + 64 + ty * 4);
            float xv[8] = {xa.x, xa.y, xa.z, xa.w, xc.x, xc.y, xc.z, xc.w};
            float wv[8] = {wa.x, wa.y, wa.z, wa.w, wc.x, wc.y, wc.z, wc.w};
#pragma unroll
            for (int i = 0; i < 8; i++)
#pragma unroll
                for (int j = 0; j < 8; j++)
                    acc[i][j] += wv[i] * xv[j];
        }

        if ((g & 31) == 31) {
            const int t = g >> 5;
            const size_t tbofs = (size_t)(t * BB + b) * CC * NN;
#pragma unroll
            for (int i = 0; i < 8; i++) {
                const int o = o0 + ((i < 4) ? (ty * 4 + i) : (64 + ty * 4 + i - 4));
                const size_t rowb = tbofs + (size_t)o * NN + n0;
#pragma unroll
                for (int hf = 0; hf < 2; hf++) {
                    const int nc = hf ? (64 + tx * 4) : (tx * 4);
                    float4 xs4;
                    if (CONN) xs4 = *(const float4*)(xsc + rowb + nc);
                    float4 r;
#pragma unroll
                    for (int j = 0; j < 4; j++) {
                        const int vi = i * 8 + hf * 4 + j;
                        float v = (t == 0) ? 0.f : Vs[vi * 256 + tid];
                        float p = acc[i][hf * 4 + j] + bb[i];
                        float chg = CONN ? (p + ((const float*)&xs4)[j]) : p;
                        v = v + (chg - v) * 0.5f;
                        float s = (v >= VTH) ? 1.f : 0.f;
                        Vs[vi * 256 + tid] = (s != 0.f) ? 0.f : v;
                        ((float*)&r)[j] = s;
                    }
                    *(float4*)(outb + rowb + nc) = r;
                }
            }
#pragma unroll
            for (int i = 0; i < 8; i++)
#pragma unroll
                for (int j = 0; j < 8; j++) acc[i][j] = 0.f;
        }

        cur = (cur == 2) ? 0 : cur + 1;
        pf = (pf == 2) ? 0 : pf + 1;
    }
}

// ---------------------------------------------------------------------------
// Fused pack + kv: per (t,b,h) block, ballot-pack K/V spike rows directly
// into smem, then kv[d][e] = popc_n(K[d] & V[e]).
// Bit map n -> (c,q,l): word c*4+q holds bit l for n = c*128 + q + l*4.
// The map is a permutation of n shared by K and V, so popc(K&V) counts
// exactly the matching n positions -> bit-exact integer counts.
// ---------------------------------------------------------------------------
__global__ __launch_bounds__(256)
void kv_pack_pop_kernel()
{
    __shared__ uint32_t Ks[64 * 33];
    __shared__ uint32_t Vt[32 * 68];

    const int tbh = blockIdx.x;
    const int tb = tbh >> 3;
    const int h = tbh & 7;
    const float* Kf = g_S + 1ull * TBCN + ((size_t)tb * CC + h * DD) * NN;
    const float* Vf = g_S + 2ull * TBCN + ((size_t)tb * CC + h * DD) * NN;

    const int tid = threadIdx.x;
    const int wp = tid >> 5, l = tid & 31;

    // phase 1: pack. warp wp handles rows wp*8 .. wp*8+7 of both K and V.
#pragma unroll
    for (int rr = 0; rr < 8; rr++) {
        const int row = wp * 8 + rr;
        const float* kr = Kf + (size_t)row * NN;
        const float* vr = Vf + (size_t)row * NN;
#pragma unroll
        for (int c = 0; c < 8; c++) {
            float4 kf = *(const float4*)(kr + c * 128 + l * 4);
            float4 vf = *(const float4*)(vr + c * 128 + l * 4);
            uint32_t k0 = __ballot_sync(0xFFFFFFFFu, kf.x != 0.f);
            uint32_t k1 = __ballot_sync(0xFFFFFFFFu, kf.y != 0.f);
            uint32_t k2 = __ballot_sync(0xFFFFFFFFu, kf.z != 0.f);
            uint32_t k3 = __ballot_sync(0xFFFFFFFFu, kf.w != 0.f);
            uint32_t v0 = __ballot_sync(0xFFFFFFFFu, vf.x != 0.f);
            uint32_t v1 = __ballot_sync(0xFFFFFFFFu, vf.y != 0.f);
            uint32_t v2 = __ballot_sync(0xFFFFFFFFu, vf.z != 0.f);
            uint32_t v3 = __ballot_sync(0xFFFFFFFFu, vf.w != 0.f);
            if (l == 0) {
                Ks[row * 33 + c * 4 + 0] = k0;
                Ks[row * 33 + c * 4 + 1] = k1;
                Ks[row * 33 + c * 4 + 2] = k2;
                Ks[row * 33 + c * 4 + 3] = k3;
                Vt[(c * 4 + 0) * 68 + row] = v0;
                Vt[(c * 4 + 1) * 68 + row] = v1;
                Vt[(c * 4 + 2) * 68 + row] = v2;
                Vt[(c * 4 + 3) * 68 + row] = v3;
            }
        }
    }
    __syncthreads();

    // phase 2: popcount GEMM
    const int d = tid >> 2;
    const int eb = (tid & 3) * 16;
    int cnt[16];
#pragma unroll
    for (int i = 0; i < 16; i++) cnt[i] = 0;

#pragma unroll 4
    for (int w = 0; w < 32; w++) {
        const uint32_t kd = Ks[d * 33 + w];
        const uint32_t* vr = &Vt[w * 68 + eb];
#pragma unroll
        for (int g = 0; g < 4; g++) {
            uint4 v4 = *(const uint4*)(vr + g * 4);
            cnt[g * 4 + 0] += __popc(kd & v4.x);
            cnt[g * 4 + 1] += __popc(kd & v4.y);
            cnt[g * 4 + 2] += __popc(kd & v4.z);
            cnt[g * 4 + 3] += __popc(kd & v4.w);
        }
    }

    float* kvout = g_kv + (size_t)tbh * DD * DD + (size_t)d * DD + eb;
#pragma unroll
    for (int g = 0; g < 4; g++) {
        float4 r = {(float)cnt[g * 4 + 0], (float)cnt[g * 4 + 1],
                    (float)cnt[g * 4 + 2], (float)cnt[g * 4 + 3]};
        *(float4*)(kvout + g * 4) = r;
    }
}

// ---------------------------------------------------------------------------
// Fused attention output + LIF. Block (n-tile 64, bh), loop t.
// Whole kv[64][68] + Q[64][68] tiles in smem: 2 barriers per t (was ~9).
// d accumulation order 0..63 sequential — identical to previous rounds.
// ---------------------------------------------------------------------------
__global__ __launch_bounds__(256)
void attn_lif_kernel()
{
    const int bh = blockIdx.y;
    const int b = bh >> 3;
    const int h = bh & 7;
    const int n0 = blockIdx.x * 64;

    __shared__ __align__(16) float kvs[DD][DD + 4];
    __shared__ __align__(16) float Qs[DD][DD + 4];

    const int tid = threadIdx.x;
    const int tx = tid & 15, ty = tid >> 4;

    float v[4][4];
#pragma unroll
    for (int i = 0; i < 4; i++)
#pragma unroll
        for (int j = 0; j < 4; j++) v[i][j] = 0.f;

    for (int t = 0; t < TT; t++) {
        const int tb = t * BB + b;
        const float* Q_ = g_S + ((size_t)tb * CC + h * DD) * NN;
        const float* kvp = g_kv + (size_t)(t * 128 + bh) * DD * DD;

        // fill kv tile and Q tile (4096 floats each)
#pragma unroll
        for (int r = 0; r < 4; r++) {
            int fid = r * 256 + tid;
            int dd = fid >> 4;
            int eg = (fid & 15) * 4;
            float4 vv = *(const float4*)(kvp + (size_t)dd * DD + eg);
            *(float4*)(&kvs[dd][eg]) = vv;
            float4 qv = *(const float4*)(Q_ + (size_t)dd * NN + n0 + eg);
            *(float4*)(&Qs[dd][eg]) = qv;
        }
        __syncthreads();

        float acc[4][4] = {};
#pragma unroll 8
        for (int kk = 0; kk < DD; kk++) {
            float4 qf = *(const float4*)(&Qs[kk][tx * 4]);
            float4 kf = *(const float4*)(&kvs[kk][ty * 4]);
            float qa[4] = {qf.x, qf.y, qf.z, qf.w};
            float ka[4] = {kf.x, kf.y, kf.z, kf.w};
#pragma unroll
            for (int i = 0; i < 4; i++)
#pragma unroll
                for (int j = 0; j < 4; j++)
                    acc[i][j] += ka[i] * qa[j];
        }
        __syncthreads();

#pragma unroll
        for (int i = 0; i < 4; i++) {
            const int e = ty * 4 + i;
            float4 r;
#pragma unroll
            for (int j = 0; j < 4; j++) {
                float xx = acc[i][j] * 0.125f;
                float vv = v[i][j];
                vv = vv + (xx - vv) * 0.5f;
                float s = (vv >= VTH) ? 1.f : 0.f;
                v[i][j] = (s != 0.f) ? 0.f : vv;
                ((float*)&r)[j] = s;
            }
            *(float4*)(g_Sa + ((size_t)tb * CC + h * DD + e) * NN + n0 + tx * 4) = r;
        }
    }
}

// ---------------------------------------------------------------------------
extern "C" void kernel_launch(void* const* d_in, const int* in_sizes, int n_in,
                              void* d_out, int out_size)
{
    const float* x  = (const float*)d_in[0];
    const float* Wq = (const float*)d_in[1];
    const float* bq = (const float*)d_in[2];
    const float* Wk = (const float*)d_in[3];
    const float* bk = (const float*)d_in[4];
    const float* Wv = (const float*)d_in[5];
    const float* bv = (const float*)d_in[6];
    const float* Wp = (const float*)d_in[7];
    const float* bp = (const float*)d_in[8];
    float* out = (float*)d_out;

    void *pS, *pSa, *pWt;
    cudaGetSymbolAddress(&pS, g_S);
    cudaGetSymbolAddress(&pSa, g_Sa);
    cudaGetSymbolAddress(&pWt, g_Wt);

    const int GL_SMEM = (12288 + 16384) * 4;  // 114688 bytes (3 stages + Vs)
    cudaFuncSetAttribute(gemm_lif<0>, cudaFuncAttributeMaxDynamicSharedMemorySize, GL_SMEM);
    cudaFuncSetAttribute(gemm_lif<1>, cudaFuncAttributeMaxDynamicSharedMemorySize, GL_SMEM);

    // 1. one-shot weight transpose (Wt[c][o])
    wtrans_kernel<<<dim3(16, 16, 4), 256>>>(Wq, Wk, Wv, Wp);
    // 2. fused QKV conv GEMM + LIF (q,k,v in one launch; bit-exact chains)
    gemm_lif<0><<<dim3(8, 4, 48), 256, GL_SMEM>>>(
        x, (const float*)pWt, 0, bq, bk, bv, nullptr, (float*)pS);
    // 3. fused pack + kv popcount (bit-exact integer counts)
    kv_pack_pop_kernel<<<TT * BB * HEADS, 256>>>();
    // 4. fused attention output + LIF
    attn_lif_kernel<<<dim3(NN / 64, BB * HEADS), 256>>>();
    // 5. fused proj conv GEMM + connecting LIF -> final spikes
    gemm_lif<1><<<dim3(8, 4, 16), 256, GL_SMEM>>>(
        (const float*)pSa, (const float*)pWt, 3, bp, bp, bp, x, out);
}